// round 3
// baseline (speedup 1.0000x reference)
#include <cuda_runtime.h>
#include <cstdint>

#define E_TOT   30000
#define NB      10
#define HID     16
#define WNUM    9216
#define EB      32
#define NTHR    256
#define INV_S3  0.5773502691896258f
#define PW0     0.10206207261596575f
#define PW1     0.17677669529663687f

typedef unsigned long long u64;

__device__ __forceinline__ u64 pk2(float lo, float hi) {
    u64 r; asm("mov.b64 %0, {%1,%2};" : "=l"(r) : "f"(lo), "f"(hi)); return r;
}
__device__ __forceinline__ void up2(u64 v, float& lo, float& hi) {
    asm("mov.b64 {%0,%1}, %2;" : "=f"(lo), "=f"(hi) : "l"(v));
}
__device__ __forceinline__ u64 fma2(u64 a, u64 b, u64 c) {
    u64 d; asm("fma.rn.f32x2 %0, %1, %2, %3;" : "=l"(d) : "l"(a), "l"(b), "l"(c)); return d;
}
__device__ __forceinline__ void cpa16(uint32_t s, const void* g) {
    asm volatile("cp.async.cg.shared.global [%0], [%1], 16;" :: "r"(s), "l"(g));
}
#define CP_COMMIT()  asm volatile("cp.async.commit_group;")
#define CP_WAIT(n)   asm volatile("cp.async.wait_group %0;" :: "n"(n))

// SMEM layout (float offsets):
//   hS  [16][EB]     @ 0
//   zA  [96][EB]     @ 512
//   zB  [64][EB]     @ 3584
//   xc  [96][EB]     @ 5632
//   sh0 [EB]         @ 8704
//   sh1 [3][EB]      @ 8736
//   w2s 2x[17][8][64]@ 8832   (double buffer; k=16 row = b2)
#define W2S_OFF     8832
#define W2S_CHUNK_A 8704          // 17*8*64
#define W2S_CHUNK_B 4352          // 17*8*32
#define SMEM_FLOATS (W2S_OFF + 2*W2S_CHUNK_A)
#define SMEM_BYTES  (SMEM_FLOATS * 4)

extern __shared__ float smem[];

__global__ void __launch_bounds__(NTHR, 2) conv_fused_kernel(
    const float* __restrict__ x,   const float* __restrict__ rps,
    const float* __restrict__ dist,const float* __restrict__ freq,
    const float* __restrict__ w1,  const float* __restrict__ b1,
    const float* __restrict__ w2,  const float* __restrict__ b2,
    float* __restrict__ out)
{
    float* hS  = smem;
    float* zA  = smem + 512;
    float* zB  = smem + 3584;
    float* xc  = smem + 5632;
    float* sh0 = smem + 8704;
    float* sh1 = smem + 8736;
    float* w2s = smem + W2S_OFF;

    const uint32_t w2s_s = (uint32_t)__cvta_generic_to_shared(w2s);

    const int t  = threadIdx.x;
    const int e0 = blockIdx.x * EB;

    // ---- async stagers (cp.async, 16B) ----
    auto stageA = [&](int uc, int buf) {
        uint32_t dst0 = w2s_s + (uint32_t)(buf * W2S_CHUNK_A) * 4u;
        for (int q4 = t; q4 < W2S_CHUNK_A / 4; q4 += NTHR) {
            int q = q4 * 4;
            int k = q >> 9;
            int r = q & 511;
            int u = r >> 6;
            int w = r & 63;
            int up = uc*8 + u;
            int j  = (up < 64) ? (up*64 + w) : (7168 + (up-64)*64 + w);
            const float* srcp = (k < 16) ? (w2 + k*WNUM + j) : (b2 + j);
            cpa16(dst0 + (uint32_t)q4 * 16u, srcp);
        }
    };
    auto stageB = [&](int uc, int buf) {
        uint32_t dst0 = w2s_s + (uint32_t)(buf * W2S_CHUNK_B) * 4u;
        for (int q4 = t; q4 < W2S_CHUNK_B / 4; q4 += NTHR) {
            int q = q4 * 4;
            int k = q >> 8;
            int r = q & 255;
            int u = r >> 5;
            int w = r & 31;
            int up = uc*8 + u;
            int j  = (up < 64) ? (4096 + up*32 + w) : (6144 + (up-64)*32 + w);
            const float* srcp = (k < 16) ? (w2 + k*WNUM + j) : (b2 + j);
            cpa16(dst0 + (uint32_t)q4 * 16u, srcp);
        }
    };

    // prefetch A-chunk 0 immediately — overlaps with all setup below
    stageA(0, 0);
    CP_COMMIT();

    // ---------------- setup: per-edge radial MLP + sh ----------------
    if (t < EB) {
        int e = e0 + t;
        if (e < E_TOT) {
            float d  = dist[e] * 0.25f;
            float id = 1.0f / d;
            float d2 = d * d;
            float d5 = d2 * d2 * d;
            float env = id - 28.0f*d5 + 48.0f*d5*d - 21.0f*d5*d2;
            env = (d < 1.0f) ? env : 0.0f;
            float basis[NB];
            #pragma unroll
            for (int i = 0; i < NB; i++) basis[i] = env * sinf(freq[i] * d);
            #pragma unroll
            for (int k = 0; k < HID; k++) {
                float pre = b1[k];
                #pragma unroll
                for (int i = 0; i < NB; i++) pre = fmaf(basis[i], w1[i*HID + k], pre);
                float s = 1.0f / (1.0f + expf(-pre));
                hS[k*EB + t] = pre * s;
            }
            sh0[t]        = rps[e*4 + 0];
            sh1[0*EB + t] = rps[e*4 + 1];
            sh1[1*EB + t] = rps[e*4 + 2];
            sh1[2*EB + t] = rps[e*4 + 3];
        } else {
            #pragma unroll
            for (int k = 0; k < HID; k++) hS[k*EB + t] = 0.0f;
            sh0[t] = 0.0f; sh1[t] = 0.0f; sh1[EB + t] = 0.0f; sh1[2*EB + t] = 0.0f;
        }
    }
    __syncthreads();

    // ---------------- setup: x tiles ----------------
    for (int idx = t; idx < EB*160; idx += NTHR) {
        int el = idx / 160, c = idx - el*160;
        int e  = e0 + el;
        float v = (e < E_TOT) ? x[e*160 + c] : 0.0f;
        if (c < 64) {
            zB[c*EB + el] = v;
            zA[c*EB + el] = v * sh0[el];
        } else {
            xc[(c-64)*EB + el] = v;
        }
    }
    __syncthreads();
    for (int idx = t; idx < 32*EB; idx += NTHR) {
        int u = idx >> 5, el = idx & (EB-1);
        float a = xc[(u*3+0)*EB+el]*sh1[0*EB+el]
                + xc[(u*3+1)*EB+el]*sh1[1*EB+el]
                + xc[(u*3+2)*EB+el]*sh1[2*EB+el];
        zA[(64+u)*EB + el] = INV_S3 * a;
    }

    // ---------------- Phase A: out0 (Wa + Wd), 64 output cols ----------------
    {
        const int tw = t & 63;
        const int tg = t >> 6;
        u64 acc0[4] = {0ull,0ull,0ull,0ull};

        for (int uc = 0; uc < 12; uc++) {
            if (uc + 1 < 12) {
                stageA(uc + 1, (uc + 1) & 1);
                CP_COMMIT();
                CP_WAIT(1);
            } else {
                CP_WAIT(0);
            }
            __syncthreads();
            const float* wb = w2s + (uc & 1) * W2S_CHUNK_A;

            u64 wgt[4][8];
            #pragma unroll
            for (int u = 0; u < 8; u++) {
                float b = wb[(16*8 + u)*64 + tw];
                u64 bb = pk2(b, b);
                #pragma unroll
                for (int p = 0; p < 4; p++) wgt[p][u] = bb;
            }
            #pragma unroll
            for (int k = 0; k < 16; k++) {
                u64 hv[4];
                #pragma unroll
                for (int p = 0; p < 4; p++)
                    hv[p] = *(const u64*)&hS[k*EB + tg*8 + 2*p];
                #pragma unroll
                for (int u = 0; u < 8; u++) {
                    float wv = wb[(k*8 + u)*64 + tw];
                    u64 wv2 = pk2(wv, wv);
                    #pragma unroll
                    for (int p = 0; p < 4; p++)
                        wgt[p][u] = fma2(hv[p], wv2, wgt[p][u]);
                }
            }
            #pragma unroll
            for (int u = 0; u < 8; u++) {
                #pragma unroll
                for (int p = 0; p < 4; p++) {
                    u64 zv = *(const u64*)&zA[(uc*8+u)*EB + tg*8 + 2*p];
                    acc0[p] = fma2(wgt[p][u], zv, acc0[p]);
                }
            }
            __syncthreads();
        }
        #pragma unroll
        for (int p = 0; p < 4; p++) {
            float lo, hi; up2(acc0[p], lo, hi);
            int eA = e0 + tg*8 + 2*p;
            if (eA     < E_TOT) out[(size_t)eA*160 + tw]     = PW0 * lo;
            if (eA + 1 < E_TOT) out[(size_t)(eA+1)*160 + tw] = PW0 * hi;
        }
    }

    // ---------------- Phase B: out1 (Wb + Wc), 32 output cols x 3 ----------------
    {
        const int tw2 = t & 31;
        const int tg2 = t >> 5;
        u64 pb[2]    = {0ull,0ull};
        u64 pc[2][3] = {{0ull,0ull,0ull},{0ull,0ull,0ull}};

        // prologue prefetch for phase B (buffers free after phase-A end barrier)
        stageB(0, 0);
        CP_COMMIT();

        for (int uc = 0; uc < 12; uc++) {
            if (uc + 1 < 12) {
                stageB(uc + 1, (uc + 1) & 1);
                CP_COMMIT();
                CP_WAIT(1);
            } else {
                CP_WAIT(0);
            }
            __syncthreads();
            const float* wb = w2s + (uc & 1) * W2S_CHUNK_B;

            u64 wgt[2][8];
            #pragma unroll
            for (int u = 0; u < 8; u++) {
                float b = wb[(16*8 + u)*32 + tw2];
                u64 bb = pk2(b, b);
                wgt[0][u] = bb; wgt[1][u] = bb;
            }
            #pragma unroll
            for (int k = 0; k < 16; k++) {
                u64 hv0 = *(const u64*)&hS[k*EB + tg2*4 + 0];
                u64 hv1 = *(const u64*)&hS[k*EB + tg2*4 + 2];
                #pragma unroll
                for (int u = 0; u < 8; u++) {
                    float wv = wb[(k*8 + u)*32 + tw2];
                    u64 wv2 = pk2(wv, wv);
                    wgt[0][u] = fma2(hv0, wv2, wgt[0][u]);
                    wgt[1][u] = fma2(hv1, wv2, wgt[1][u]);
                }
            }
            if (uc < 8) {
                #pragma unroll
                for (int u = 0; u < 8; u++) {
                    #pragma unroll
                    for (int p = 0; p < 2; p++) {
                        u64 zv = *(const u64*)&zB[(uc*8+u)*EB + tg2*4 + 2*p];
                        pb[p] = fma2(wgt[p][u], zv, pb[p]);
                    }
                }
            } else {
                #pragma unroll
                for (int u = 0; u < 8; u++) {
                    int u0 = (uc-8)*8 + u;
                    #pragma unroll
                    for (int m = 0; m < 3; m++) {
                        #pragma unroll
                        for (int p = 0; p < 2; p++) {
                            u64 xv = *(const u64*)&xc[(u0*3+m)*EB + tg2*4 + 2*p];
                            pc[p][m] = fma2(wgt[p][u], xv, pc[p][m]);
                        }
                    }
                }
            }
            __syncthreads();
        }
        #pragma unroll
        for (int p = 0; p < 2; p++) {
            float pbl, pbh; up2(pb[p], pbl, pbh);
            float pcl[3], pch[3];
            #pragma unroll
            for (int m = 0; m < 3; m++) up2(pc[p][m], pcl[m], pch[m]);
            int el = tg2*4 + 2*p;
            int e  = e0 + el;
            float s0l = sh0[el], s0h = sh0[el+1];
            if (e < E_TOT) {
                #pragma unroll
                for (int m = 0; m < 3; m++)
                    out[(size_t)e*160 + 64 + tw2*3 + m] =
                        (PW1*INV_S3) * (pbl*sh1[m*EB + el] + pcl[m]*s0l);
            }
            if (e + 1 < E_TOT) {
                #pragma unroll
                for (int m = 0; m < 3; m++)
                    out[(size_t)(e+1)*160 + 64 + tw2*3 + m] =
                        (PW1*INV_S3) * (pbh*sh1[m*EB + el + 1] + pch[m]*s0h);
            }
        }
    }
}

extern "C" void kernel_launch(void* const* d_in, const int* in_sizes, int n_in,
                              void* d_out, int out_size) {
    (void)in_sizes; (void)n_in; (void)out_size;
    const float* x    = (const float*)d_in[0];
    const float* rps  = (const float*)d_in[1];
    const float* dist = (const float*)d_in[2];
    const float* freq = (const float*)d_in[3];
    const float* w1   = (const float*)d_in[4];
    const float* b1   = (const float*)d_in[5];
    const float* w2   = (const float*)d_in[6];
    const float* b2   = (const float*)d_in[7];
    float* out = (float*)d_out;

    cudaFuncSetAttribute(conv_fused_kernel,
                         cudaFuncAttributeMaxDynamicSharedMemorySize, SMEM_BYTES);

    const int nblocks = (E_TOT + EB - 1) / EB;   // 938
    conv_fused_kernel<<<nblocks, NTHR, SMEM_BYTES>>>(
        x, rps, dist, freq, w1, b1, w2, b2, out);
}